// round 8
// baseline (speedup 1.0000x reference)
#include <cuda_runtime.h>

// ConvNearestNeightbor: out[b, n*C+c, h, w] = max_k |x_pad[b,c,h-row,w-col] - nb[n,c,k]|
// Model (R8): fma-pipe demand 15.9K cyc/SMSP + alu 14.2K; ideal interleave ~16K cycles
// (8.4us) but measured 27K -> pipes barely overlap because each iter's 3 LDS (29cyc)
// stall the FADD wave. Fix: software-pipeline the neighbor loads one iteration ahead
// and remove the store-pointer dependency chain (immediate offsets).

namespace {

constexpr int B = 16, C = 32, H = 32, W = 32, NUM = 32;
constexpr int HW = H * W;
constexpr int NSPLIT = 2;
constexpr int NPER = NUM / NSPLIT;  // 16

// max(|a|,|b|) -> single FMNMX with |src| modifiers on both operands (alu pipe)
__device__ __forceinline__ float maxabs(float a, float b) {
  return fmaxf(fabsf(a), fabsf(b));
}

__global__ __launch_bounds__(256, 5) void cnn_kernel(
    const float* __restrict__ x,
    const float* __restrict__ nb,
    float* __restrict__ out) {
  __shared__ __align__(16) float xs[34 * 36];      // halo tile, padded rows (36 floats)
  __shared__ __align__(16) float nbs[NPER * 12];   // 9 taps padded to 12 -> LDS.128

  const int bc = blockIdx.x;   // 0 .. B*C-1
  const int ns = blockIdx.y;   // 0 .. NSPLIT-1
  const int c  = bc & (C - 1);
  const int b  = bc / C;
  const int tid = threadIdx.x;

  const int h  = tid >> 3;          // 0..31  (also interior-load row)
  const int wq = (tid & 7) << 2;    // 0,4,...,28

  // ---- neighbors first (latency hides under the x-tile load) ----
  if (tid < NPER * 9) {  // 144 scalars
    int nn = tid / 9;
    int k  = tid - nn * 9;
    nbs[nn * 12 + k] = nb[(size_t)(ns * NPER + nn) * (C * 9) + c * 9 + k];
  }

  // ---- x tile: 1 vector LDG per thread + predicated halo zeros ----
  const float* xp = x + (size_t)bc * HW;
  {
    float4 v = *(const float4*)(xp + h * W + wq);
    float* dst = &xs[(h + 1) * 36 + wq + 1];
    dst[0] = v.x; dst[1] = v.y; dst[2] = v.z; dst[3] = v.w;
  }
  if (tid < 132) {  // halo cells: rows 0,33 cols 0..33; cols 0,33 rows 1..32
    int rr, cc;
    if (tid < 68)        { rr = (tid < 34) ? 0 : 33; cc = (tid < 34) ? tid : tid - 34; }
    else if (tid < 100)  { rr = tid - 68 + 1;  cc = 0; }
    else                 { rr = tid - 100 + 1; cc = 33; }
    xs[rr * 36 + cc] = 0.f;
  }
  __syncthreads();

  // hoist the 3x6 x-window into registers (reused across all NPER n)
  float xv[3][6];
#pragma unroll
  for (int r = 0; r < 3; r++) {
    const float* p = &xs[(h + r) * 36 + wq];
    float4 v4 = *(const float4*)p;
    float2 v2 = *(const float2*)(p + 4);
    xv[r][0] = v4.x; xv[r][1] = v4.y; xv[r][2] = v4.z; xv[r][3] = v4.w;
    xv[r][4] = v2.x; xv[r][5] = v2.y;
  }

  float* const outp =
      out + ((size_t)(b * NUM + ns * NPER) * C + c) * HW + h * W + wq;

  // ---- software pipeline: neighbors for iter nn+1 prefetched during iter nn ----
  float4 pn0 = *(const float4*)&nbs[0];
  float4 pn1 = *(const float4*)&nbs[4];
  float  pn8 = nbs[8];

#pragma unroll
  for (int nn = 0; nn < NPER; nn++) {
    // current iteration's neighbor values (from prefetch registers)
    const float nv[9] = {pn0.x, pn0.y, pn0.z, pn0.w,
                         pn1.x, pn1.y, pn1.z, pn1.w, pn8};

    // issue next iteration's LDS NOW — consumers are ~140 cycles away
    if (nn + 1 < NPER) {
      pn0 = *(const float4*)&nbs[(nn + 1) * 12];
      pn1 = *(const float4*)&nbs[(nn + 1) * 12 + 4];
      pn8 = nbs[(nn + 1) * 12 + 8];
    }

    float res[4];
#pragma unroll
    for (int j = 0; j < 4; j++) {
      // tap k -> window coords: r = 2 - k/3, cc = 2 - k%3, read xv[r][cc+j]
      float d[9];
#pragma unroll
      for (int k = 0; k < 9; k++) {
        const int r  = 2 - k / 3;
        const int cc = 2 - k % 3;
        d[k] = xv[r][cc + j] - nv[k];
      }
      // 8-op dual-abs max tree, depth 4 (alu pipe)
      float t0 = maxabs(d[0], d[1]);
      float t1 = maxabs(d[2], d[3]);
      float t2 = maxabs(d[4], d[5]);
      float t3 = maxabs(d[6], d[7]);
      float u0 = fmaxf(t0, t1);
      float u1 = fmaxf(t2, t3);
      res[j] = fmaxf(u0, fmaxf(u1, fabsf(d[8])));
    }
    // constant per-unrolled-iter offset -> STG [R+imm], no pointer-increment chain
    *(float4*)(outp + (size_t)nn * C * HW) = make_float4(res[0], res[1], res[2], res[3]);
  }
}

}  // namespace

extern "C" void kernel_launch(void* const* d_in, const int* in_sizes, int n_in,
                              void* d_out, int out_size) {
  const float* x  = (const float*)d_in[0];   // (B,C,H,W) fp32
  const float* nb = (const float*)d_in[1];   // (NUM,C,9) fp32
  float* out = (float*)d_out;                // (B, NUM*C, H, W) fp32
  dim3 grid(B * C, NSPLIT);
  cnn_kernel<<<grid, 256>>>(x, nb, out);
}